// round 9
// baseline (speedup 1.0000x reference)
#include <cuda_runtime.h>
#include <cstdint>

#define NB 128
#define NT 512
#define BB 16
#define TT 1024
#define DD 1024
#define SS 512
#define MM 16
#define NSLOT 22                 // 8 passB + 2x7 passA (parity double buffer)
#define CBBB 4128                // bytes per cb region, pass B staging
#define CBA  2592                // bytes per cb region, pass A staging
#define PASSA_OFF 16896          // byte offset of pass A staging in smem

// ---------------- persistent state (device globals; no allocation) ----------
__device__ float g_h[BB * DD];
__device__ float g_c[BB * DD];
__device__ float g_ctx[BB * DD];
__device__ float g_gpart[NSLOT][BB][4 * DD];   // 5.8 MB
__device__ float g_watt[BB][SS];
__device__ unsigned g_count;
__device__ int g_flags[NB * 8];

__device__ __forceinline__ float sigf(float x) {
    return __fdividef(1.0f, 1.0f + __expf(-x));
}
__device__ __forceinline__ float tanhfast(float x) {
    const float xc = fminf(fmaxf(x, -15.0f), 15.0f);
    const float e  = __expf(2.0f * xc);
    return __fdividef(e - 1.0f, e + 1.0f);
}

// Grid barrier with distributed release. 128 blocks, single wave.
__device__ __forceinline__ void grid_barrier(int gen) {
    __syncthreads();
    if (threadIdx.x == 0) {
        __threadfence();
        const unsigned arrived = atomicAdd(&g_count, 1u);
        if (arrived == NB - 1) {
            g_count = 0u;
            __threadfence();
            #pragma unroll 8
            for (int i = 0; i < NB; ++i) g_flags[i * 8] = gen;
        } else {
            volatile int* f = &g_flags[blockIdx.x * 8];
            while (*f != gen) { __nanosleep(16); }
        }
        __threadfence();
    }
    __syncthreads();
}

extern __shared__ float smem[];

__device__ __forceinline__ uint32_t swz(uint32_t L) {
    return L ^ ((L >> 3) & 0x70u);
}

__global__ __launch_bounds__(NT, 1) void tts_kernel(
    const float* __restrict__ x_in,    // [B,T,D]
    const float* __restrict__ memv,    // [B,S,D]
    const int*   __restrict__ lens,    // [B]
    const float* __restrict__ W_ih,    // [4096,2048]
    const float* __restrict__ W_hh,    // [4096,1024]
    const float* __restrict__ b_ih,    // [4096]
    const float* __restrict__ b_hh,    // [4096]
    const float* __restrict__ Wg_w,    // [48,1024]
    const float* __restrict__ Wg_b,    // [48]
    float* __restrict__ out)
{
    const int bid = blockIdx.x;
    const int tid = threadIdx.x;
    char* smb = reinterpret_cast<char*>(smem);

    // scratch after pass-B staging (4*CBBB = 16512 B -> float idx 4128)
    float* sh_phi   = smem + 4128;   // 48
    float* sh_ksi   = smem + 4176;   // 16
    float* sh_binv  = smem + 4192;   // 16
    float* sh_alpha = smem + 4208;   // 16

    float* out_ctx   = out;
    float* out_align = out + BB * DD;
    float* out_term  = out + BB * DD + (size_t)BB * TT * SS;

    int bgen = 0;

    for (int i = bid * NT + tid; i < BB * DD; i += NB * NT) {
        g_h[i] = 0.0f; g_c[i] = 0.0f; g_ctx[i] = 0.0f;
    }
    grid_barrier(++bgen);

    // thread micro-mapping (shared by both passes)
    const int jg    = tid >> 4;         // 0..31 -> 8 rows each
    const int lane4 = tid & 15;
    const int bg    = lane4 & 1;        // batches bg*8 .. bg*8+7
    const int ksl   = lane4 >> 1;       // 0..7

    // ---- pass B mapping: k in [1024,3072), 16 j-tiles x 8 k-splits of 256
    const int jt = bid >> 3;            // 0..15
    const int kb = bid & 7;             // 0..7
    const int j0 = jt * 256 + jg * 8;
    const float* wbaseB;
    int wstrideB;
    if (kb < 4) { wbaseB = W_ih + (size_t)j0 * 2048 + 1024 + kb * 256; wstrideB = 2048; }
    else        { wbaseB = W_hh + (size_t)j0 * 1024 + (kb - 4) * 256;  wstrideB = 1024; }
    const float* srcB = (kb < 4) ? (g_ctx + kb * 256) : (g_h + (kb - 4) * 256);

    // ---- pass A mapping: k in [0,1024), blocks 16..127: 16 jt x 7 k-splits
    const bool  hasA = (bid >= 16);
    const int   aix  = hasA ? (bid - 16) : 0;
    const int   jtA  = aix / 7;
    const int   kA   = aix - jtA * 7;
    const int   UA   = 9 + (kA == 6);          // ii-units of 16 k
    const int   kstartA = 144 * kA;
    const int   j0A  = jtA * 256 + jg * 8;
    const float* wbaseA = W_ih + (size_t)j0A * 2048 + kstartA;

    // ================== pass A for step 0 (pre-loop) ==================
    if (hasA) {
        const int nq = 4 * UA;               // quads per batch
        #pragma unroll
        for (int r = 0; r < 2; ++r) {
            const int qi = r * NT + tid;
            if (qi < 16 * nq) {
                const int b  = qi / nq;
                const int kq = qi - b * nq;
                const float4 v = *reinterpret_cast<const float4*>(
                    &x_in[(size_t)b * TT * DD + kstartA + kq * 4]);
                const int cb = b >> 2, bl = b & 3;
                char* base = smb + PASSA_OFF + cb * CBA;
                const int kl = kq * 4;
                *reinterpret_cast<float*>(base + swz((uint32_t)((kl + 0) * 16 + bl * 4))) = v.x;
                *reinterpret_cast<float*>(base + swz((uint32_t)((kl + 1) * 16 + bl * 4))) = v.y;
                *reinterpret_cast<float*>(base + swz((uint32_t)((kl + 2) * 16 + bl * 4))) = v.z;
                *reinterpret_cast<float*>(base + swz((uint32_t)((kl + 3) * 16 + bl * 4))) = v.w;
            }
        }
        __syncthreads();
        {
            unsigned long long acc[8][4];
            #pragma unroll
            for (int a = 0; a < 8; ++a)
                #pragma unroll
                for (int p = 0; p < 4; ++p) acc[a][p] = 0ull;
            float2 w0[8], w1[8];
            const char* xb0 = smb + PASSA_OFF + (bg * 2) * CBA;
            #pragma unroll
            for (int a = 0; a < 8; ++a)
                w0[a] = *reinterpret_cast<const float2*>(wbaseA + (size_t)a * 2048 + ksl * 2);
            for (int pp = 0; pp < UA; ++pp) {
                if (pp + 1 < UA) {
                    const int kk = ((pp + 1) * 8 + ksl) * 2;
                    #pragma unroll
                    for (int a = 0; a < 8; ++a)
                        w1[a] = *reinterpret_cast<const float2*>(wbaseA + (size_t)a * 2048 + kk);
                }
                #pragma unroll
                for (int q = 0; q < 2; ++q) {
                    const int kl = (pp * 8 + ksl) * 2 + q;
                    const uint32_t L = swz((uint32_t)(kl * 16));
                    const double2 d0 = *reinterpret_cast<const double2*>(xb0 + L);
                    const double2 d1 = *reinterpret_cast<const double2*>(xb0 + CBA + L);
                    const unsigned long long xv0 = __double_as_longlong(d0.x);
                    const unsigned long long xv1 = __double_as_longlong(d0.y);
                    const unsigned long long xv2 = __double_as_longlong(d1.x);
                    const unsigned long long xv3 = __double_as_longlong(d1.y);
                    #pragma unroll
                    for (int a = 0; a < 8; ++a) {
                        const float wv = q ? w0[a].y : w0[a].x;
                        unsigned long long w2;
                        asm("mov.b64 %0, {%1, %1};" : "=l"(w2) : "r"(__float_as_uint(wv)));
                        asm("fma.rn.f32x2 %0, %1, %2, %0;" : "+l"(acc[a][0]) : "l"(w2), "l"(xv0));
                        asm("fma.rn.f32x2 %0, %1, %2, %0;" : "+l"(acc[a][1]) : "l"(w2), "l"(xv1));
                        asm("fma.rn.f32x2 %0, %1, %2, %0;" : "+l"(acc[a][2]) : "l"(w2), "l"(xv2));
                        asm("fma.rn.f32x2 %0, %1, %2, %0;" : "+l"(acc[a][3]) : "l"(w2), "l"(xv3));
                    }
                }
                #pragma unroll
                for (int a = 0; a < 8; ++a) w0[a] = w1[a];
            }
            #pragma unroll
            for (int off = 2; off <= 8; off <<= 1) {
                #pragma unroll
                for (int a = 0; a < 8; ++a)
                    #pragma unroll
                    for (int p = 0; p < 4; ++p) {
                        unsigned lo = (unsigned)acc[a][p];
                        unsigned hi = (unsigned)(acc[a][p] >> 32);
                        lo = __shfl_xor_sync(0xFFFFFFFFu, lo, off);
                        hi = __shfl_xor_sync(0xFFFFFFFFu, hi, off);
                        unsigned long long o = ((unsigned long long)hi << 32) | lo;
                        asm("add.rn.f32x2 %0, %0, %1;" : "+l"(acc[a][p]) : "l"(o));
                    }
            }
            const int sA = 8 + kA;   // parity 0 for step 0
            #pragma unroll
            for (int a = 0; a < 8; ++a) {
                if (a == ksl) {
                    const int j = j0A + a;
                    #pragma unroll
                    for (int p = 0; p < 4; ++p) {
                        const int b0 = bg * 8 + 2 * p;
                        const unsigned long long v = acc[a][p];
                        g_gpart[sA][b0][j]     = __uint_as_float((unsigned)v);
                        g_gpart[sA][b0 + 1][j] = __uint_as_float((unsigned)(v >> 32));
                    }
                }
            }
        }
        __syncthreads();
    }

    for (int t = 0; t < TT; ++t) {
        // ============ stage ctx/h slice [16 b x 256 k] (pass B) ============
        #pragma unroll
        for (int r = 0; r < 2; ++r) {
            const int qi = r * NT + tid;         // < 1024
            const int b  = qi >> 6;
            const int kq = qi & 63;
            const float4 v = *reinterpret_cast<const float4*>(srcB + (size_t)b * DD + kq * 4);
            const int cb = b >> 2, bl = b & 3;
            char* base = smb + cb * CBBB;
            const int kl = kq * 4;
            *reinterpret_cast<float*>(base + swz((uint32_t)((kl + 0) * 16 + bl * 4))) = v.x;
            *reinterpret_cast<float*>(base + swz((uint32_t)((kl + 1) * 16 + bl * 4))) = v.y;
            *reinterpret_cast<float*>(base + swz((uint32_t)((kl + 2) * 16 + bl * 4))) = v.z;
            *reinterpret_cast<float*>(base + swz((uint32_t)((kl + 3) * 16 + bl * 4))) = v.w;
        }
        __syncthreads();

        // ================== GEMM pass B (critical path) ====================
        {
            unsigned long long acc[8][4];
            #pragma unroll
            for (int a = 0; a < 8; ++a)
                #pragma unroll
                for (int p = 0; p < 4; ++p) acc[a][p] = 0ull;

            float2 wA[8], wB[8];
            auto ldw = [&](float2* dst, int pp) {
                const int kk = (pp * 8 + ksl) * 2;
                #pragma unroll
                for (int a = 0; a < 8; ++a)
                    dst[a] = *reinterpret_cast<const float2*>(
                        wbaseB + (size_t)a * wstrideB + kk);
            };
            const char* xb0 = smb + (bg * 2) * CBBB;
            auto compute = [&](const float2* w, int pp) {
                #pragma unroll
                for (int q = 0; q < 2; ++q) {
                    const int kl = (pp * 8 + ksl) * 2 + q;
                    const uint32_t L = swz((uint32_t)(kl * 16));
                    const double2 d0 = *reinterpret_cast<const double2*>(xb0 + L);
                    const double2 d1 = *reinterpret_cast<const double2*>(xb0 + CBBB + L);
                    const unsigned long long xv0 = __double_as_longlong(d0.x);
                    const unsigned long long xv1 = __double_as_longlong(d0.y);
                    const unsigned long long xv2 = __double_as_longlong(d1.x);
                    const unsigned long long xv3 = __double_as_longlong(d1.y);
                    #pragma unroll
                    for (int a = 0; a < 8; ++a) {
                        const float wv = q ? w[a].y : w[a].x;
                        unsigned long long w2;
                        asm("mov.b64 %0, {%1, %1};" : "=l"(w2) : "r"(__float_as_uint(wv)));
                        asm("fma.rn.f32x2 %0, %1, %2, %0;" : "+l"(acc[a][0]) : "l"(w2), "l"(xv0));
                        asm("fma.rn.f32x2 %0, %1, %2, %0;" : "+l"(acc[a][1]) : "l"(w2), "l"(xv1));
                        asm("fma.rn.f32x2 %0, %1, %2, %0;" : "+l"(acc[a][2]) : "l"(w2), "l"(xv2));
                        asm("fma.rn.f32x2 %0, %1, %2, %0;" : "+l"(acc[a][3]) : "l"(w2), "l"(xv3));
                    }
                }
            };

            ldw(wA, 0);
            #pragma unroll 1
            for (int ii = 0; ii < 8; ++ii) {
                ldw(wB, 2 * ii + 1);
                compute(wA, 2 * ii);
                if (ii < 7) ldw(wA, 2 * ii + 2);
                compute(wB, 2 * ii + 1);
            }

            #pragma unroll
            for (int off = 2; off <= 8; off <<= 1) {
                #pragma unroll
                for (int a = 0; a < 8; ++a)
                    #pragma unroll
                    for (int p = 0; p < 4; ++p) {
                        unsigned lo = (unsigned)acc[a][p];
                        unsigned hi = (unsigned)(acc[a][p] >> 32);
                        lo = __shfl_xor_sync(0xFFFFFFFFu, lo, off);
                        hi = __shfl_xor_sync(0xFFFFFFFFu, hi, off);
                        unsigned long long o = ((unsigned long long)hi << 32) | lo;
                        asm("add.rn.f32x2 %0, %0, %1;" : "+l"(acc[a][p]) : "l"(o));
                    }
            }
            #pragma unroll
            for (int a = 0; a < 8; ++a) {
                if (a == ksl) {
                    const int j = j0 + a;
                    #pragma unroll
                    for (int p = 0; p < 4; ++p) {
                        const int b0 = bg * 8 + 2 * p;
                        const unsigned long long v = acc[a][p];
                        g_gpart[kb][b0][j]     = __uint_as_float((unsigned)v);
                        g_gpart[kb][b0 + 1][j] = __uint_as_float((unsigned)(v >> 32));
                    }
                }
            }
        }
        grid_barrier(++bgen);  // B1: gates(t) complete

        // ===== phase 2: LSTM/phi/attn (blocks 0..15) || pass A(t+1) ========
        if (bid < BB) {
            const int b = bid;
            const int abase = 8 + (t & 1) * 7;
            #pragma unroll
            for (int r = 0; r < 2; ++r) {
                const int dd = r * NT + tid;
                float gi = b_ih[dd]          + b_hh[dd];
                float gf = b_ih[DD + dd]     + b_hh[DD + dd];
                float gg = b_ih[2 * DD + dd] + b_hh[2 * DD + dd];
                float go = b_ih[3 * DD + dd] + b_hh[3 * DD + dd];
                #pragma unroll
                for (int q = 0; q < 8; ++q) {
                    gi += g_gpart[q][b][dd];
                    gf += g_gpart[q][b][DD + dd];
                    gg += g_gpart[q][b][2 * DD + dd];
                    go += g_gpart[q][b][3 * DD + dd];
                }
                #pragma unroll
                for (int q = 0; q < 7; ++q) {
                    gi += g_gpart[abase + q][b][dd];
                    gf += g_gpart[abase + q][b][DD + dd];
                    gg += g_gpart[abase + q][b][2 * DD + dd];
                    go += g_gpart[abase + q][b][3 * DD + dd];
                }
                const float c = sigf(gf) * g_c[b * DD + dd] + sigf(gi) * tanhfast(gg);
                const float h = sigf(go) * tanhfast(c);
                g_c[b * DD + dd] = c;
                g_h[b * DD + dd] = h;
            }
            __syncthreads();

            // phi = h @ Wg_w^T + Wg_b
            {
                const int w = tid >> 5, lane = tid & 31;
                float hreg[32];
                #pragma unroll
                for (int i = 0; i < 32; ++i) hreg[i] = g_h[b * DD + i * 32 + lane];
                #pragma unroll
                for (int mi = 0; mi < 3; ++mi) {
                    const int mm = w * 3 + mi;
                    const float* wr = Wg_w + (size_t)mm * DD;
                    float acc = 0.0f;
                    #pragma unroll
                    for (int i = 0; i < 32; ++i) acc += wr[i * 32 + lane] * hreg[i];
                    #pragma unroll
                    for (int off = 16; off; off >>= 1)
                        acc += __shfl_xor_sync(0xFFFFFFFFu, acc, off);
                    if (lane == 0) sh_phi[mm] = acc + Wg_b[mm];
                }
            }
            __syncthreads();

            if (tid < 32) {
                const int m = tid & 15;
                const float pk = sh_phi[m];
                const float pb = sh_phi[MM + m];
                const float pa = sh_phi[2 * MM + m];
                float mx = pa;
                #pragma unroll
                for (int off = 1; off < 16; off <<= 1)
                    mx = fmaxf(mx, __shfl_xor_sync(0xFFFFFFFFu, mx, off, 16));
                const float e = __expf(pa - mx);
                float sum = e;
                #pragma unroll
                for (int off = 1; off < 16; off <<= 1)
                    sum += __shfl_xor_sync(0xFFFFFFFFu, sum, off, 16);
                if (tid < 16) {
                    sh_alpha[m] = e / sum;
                    sh_ksi[m]   = __expf(pk);
                    sh_binv[m]  = __expf(-pb);
                }
            }
            __syncthreads();

            {
                const int s = tid & (SS - 1);
                const int lb = lens[b];
                const float fs = (float)s;
                float aw = 0.0f, ar = 0.0f;
                #pragma unroll
                for (int m = 0; m < MM; ++m) {
                    const float binv = sh_binv[m];
                    const float z  = (fs - sh_ksi[m]) * binv;
                    const float hb = 0.5f * binv;
                    const float fr = sigf(z + hb);
                    const float fl = sigf(z - hb);
                    const float al = sh_alpha[m];
                    aw += al * (fr - fl);
                    ar += al * fr;
                }
                g_watt[b][s] = aw;
                out_align[((size_t)b * TT + t) * SS + s] = aw;
                if (t == TT - 1 && s == lb - 1) out_term[b] = 1.0f - ar;
            }
        } else if (t + 1 < TT) {
            // ---------------- pass A for step t+1 (blocks 16..127) ---------
            const int nq = 4 * UA;
            #pragma unroll
            for (int r = 0; r < 2; ++r) {
                const int qi = r * NT + tid;
                if (qi < 16 * nq) {
                    const int b  = qi / nq;
                    const int kq = qi - b * nq;
                    const float4 v = *reinterpret_cast<const float4*>(
                        &x_in[((size_t)b * TT + (t + 1)) * DD + kstartA + kq * 4]);
                    const int cb = b >> 2, bl = b & 3;
                    char* base = smb + PASSA_OFF + cb * CBA;
                    const int kl = kq * 4;
                    *reinterpret_cast<float*>(base + swz((uint32_t)((kl + 0) * 16 + bl * 4))) = v.x;
                    *reinterpret_cast<float*>(base + swz((uint32_t)((kl + 1) * 16 + bl * 4))) = v.y;
                    *reinterpret_cast<float*>(base + swz((uint32_t)((kl + 2) * 16 + bl * 4))) = v.z;
                    *reinterpret_cast<float*>(base + swz((uint32_t)((kl + 3) * 16 + bl * 4))) = v.w;
                }
            }
            __syncthreads();
            unsigned long long acc[8][4];
            #pragma unroll
            for (int a = 0; a < 8; ++a)
                #pragma unroll
                for (int p = 0; p < 4; ++p) acc[a][p] = 0ull;
            float2 w0[8], w1[8];
            const char* xb0 = smb + PASSA_OFF + (bg * 2) * CBA;
            #pragma unroll
            for (int a = 0; a < 8; ++a)
                w0[a] = *reinterpret_cast<const float2*>(wbaseA + (size_t)a * 2048 + ksl * 2);
            for (int pp = 0; pp < UA; ++pp) {
                if (pp + 1 < UA) {
                    const int kk = ((pp + 1) * 8 + ksl) * 2;
                    #pragma unroll
                    for (int a = 0; a < 8; ++a)
                        w1[a] = *reinterpret_cast<const float2*>(wbaseA + (size_t)a * 2048 + kk);
                }
                #pragma unroll
                for (int q = 0; q < 2; ++q) {
                    const int kl = (pp * 8 + ksl) * 2 + q;
                    const uint32_t L = swz((uint32_t)(kl * 16));
                    const double2 d0 = *reinterpret_cast<const double2*>(xb0 + L);
                    const double2 d1 = *reinterpret_cast<const double2*>(xb0 + CBA + L);
                    const unsigned long long xv0 = __double_as_longlong(d0.x);
                    const unsigned long long xv1 = __double_as_longlong(d0.y);
                    const unsigned long long xv2 = __double_as_longlong(d1.x);
                    const unsigned long long xv3 = __double_as_longlong(d1.y);
                    #pragma unroll
                    for (int a = 0; a < 8; ++a) {
                        const float wv = q ? w0[a].y : w0[a].x;
                        unsigned long long w2;
                        asm("mov.b64 %0, {%1, %1};" : "=l"(w2) : "r"(__float_as_uint(wv)));
                        asm("fma.rn.f32x2 %0, %1, %2, %0;" : "+l"(acc[a][0]) : "l"(w2), "l"(xv0));
                        asm("fma.rn.f32x2 %0, %1, %2, %0;" : "+l"(acc[a][1]) : "l"(w2), "l"(xv1));
                        asm("fma.rn.f32x2 %0, %1, %2, %0;" : "+l"(acc[a][2]) : "l"(w2), "l"(xv2));
                        asm("fma.rn.f32x2 %0, %1, %2, %0;" : "+l"(acc[a][3]) : "l"(w2), "l"(xv3));
                    }
                }
                #pragma unroll
                for (int a = 0; a < 8; ++a) w0[a] = w1[a];
            }
            #pragma unroll
            for (int off = 2; off <= 8; off <<= 1) {
                #pragma unroll
                for (int a = 0; a < 8; ++a)
                    #pragma unroll
                    for (int p = 0; p < 4; ++p) {
                        unsigned lo = (unsigned)acc[a][p];
                        unsigned hi = (unsigned)(acc[a][p] >> 32);
                        lo = __shfl_xor_sync(0xFFFFFFFFu, lo, off);
                        hi = __shfl_xor_sync(0xFFFFFFFFu, hi, off);
                        unsigned long long o = ((unsigned long long)hi << 32) | lo;
                        asm("add.rn.f32x2 %0, %0, %1;" : "+l"(acc[a][p]) : "l"(o));
                    }
            }
            const int sA = 8 + ((t + 1) & 1) * 7 + kA;
            #pragma unroll
            for (int a = 0; a < 8; ++a) {
                if (a == ksl) {
                    const int j = j0A + a;
                    #pragma unroll
                    for (int p = 0; p < 4; ++p) {
                        const int b0 = bg * 8 + 2 * p;
                        const unsigned long long v = acc[a][p];
                        g_gpart[sA][b0][j]     = __uint_as_float((unsigned)v);
                        g_gpart[sA][b0 + 1][j] = __uint_as_float((unsigned)(v >> 32));
                    }
                }
            }
        }
        grid_barrier(++bgen);  // B2: h, watt (and pass A(t+1)) ready

        // ===================== ctx = w @ memory ============================
        {
            const int b  = bid >> 3;
            const int d0 = (bid & 7) * 128;
            const int w  = tid >> 5, lane = tid & 31;
            const float* mb = memv + (size_t)b * SS * DD + d0 + lane * 4;
            float4 acc = make_float4(0.f, 0.f, 0.f, 0.f);
            const int sbase = w * 32;
            #pragma unroll 4
            for (int si = 0; si < 32; ++si) {
                const int s = sbase + si;
                const float wv = g_watt[b][s];
                const float4 mv = *reinterpret_cast<const float4*>(mb + (size_t)s * DD);
                acc.x += wv * mv.x; acc.y += wv * mv.y;
                acc.z += wv * mv.z; acc.w += wv * mv.w;
            }
            float4* red = reinterpret_cast<float4*>(smem);
            red[w * 32 + lane] = acc;
            __syncthreads();
            if (tid < 32) {
                float4 r = red[tid];
                #pragma unroll
                for (int q = 1; q < 16; ++q) {
                    const float4 v = red[q * 32 + tid];
                    r.x += v.x; r.y += v.y; r.z += v.z; r.w += v.w;
                }
                const int di = d0 + tid * 4;
                *reinterpret_cast<float4*>(&g_ctx[b * DD + di]) = r;
                if (t == TT - 1)
                    *reinterpret_cast<float4*>(&out_ctx[b * DD + di]) = r;
            }
        }
        grid_barrier(++bgen);  // B3: ctx ready
    }
}

extern "C" void kernel_launch(void* const* d_in, const int* in_sizes, int n_in,
                              void* d_out, int out_size) {
    (void)in_sizes; (void)n_in; (void)out_size;
    const float* x_in  = (const float*)d_in[0];
    const float* memv  = (const float*)d_in[1];
    const int*   lens  = (const int*)  d_in[2];
    const float* W_ih  = (const float*)d_in[3];
    const float* W_hh  = (const float*)d_in[4];
    const float* b_ih  = (const float*)d_in[5];
    const float* b_hh  = (const float*)d_in[6];
    const float* Wg_w  = (const float*)d_in[7];
    const float* Wg_b  = (const float*)d_in[8];
    tts_kernel<<<NB, NT, 28672>>>(x_in, memv, lens, W_ih, W_hh,
                                  b_ih, b_hh, Wg_w, Wg_b, (float*)d_out);
}

// round 10
// speedup vs baseline: 1.0453x; 1.0453x over previous
#include <cuda_runtime.h>
#include <cstdint>
#include <cstdio>

#define NB 128
#define NT 512
#define BB 16
#define TT 1024
#define DD 1024
#define SS 512
#define MM 16
#define KSPLIT 8
#define KBL 384                    // k per block
#define CBB 6176                   // bytes per cb staging region (6144 + pad)

// ---------------- persistent state (device globals; no allocation) ----------
__device__ float g_h[BB * DD];
__device__ float g_c[BB * DD];
__device__ float g_ctx[BB * DD];
__device__ float g_gpart[KSPLIT][BB][4 * DD];   // 2 MB
__device__ float g_watt[BB][SS];
__device__ unsigned g_count;
__device__ int g_flags[NB * 8];

__device__ __forceinline__ float sigf(float x) {
    return __fdividef(1.0f, 1.0f + __expf(-x));
}
__device__ __forceinline__ float tanhfast(float x) {
    const float xc = fminf(fmaxf(x, -15.0f), 15.0f);
    const float e  = __expf(2.0f * xc);
    return __fdividef(e - 1.0f, e + 1.0f);
}

// Grid barrier with distributed release. 128 blocks, single wave.
__device__ __forceinline__ void grid_barrier(int gen) {
    __syncthreads();
    if (threadIdx.x == 0) {
        __threadfence();
        const unsigned arrived = atomicAdd(&g_count, 1u);
        if (arrived == NB - 1) {
            g_count = 0u;
            __threadfence();
            #pragma unroll 8
            for (int i = 0; i < NB; ++i) g_flags[i * 8] = gen;
        } else {
            volatile int* f = &g_flags[blockIdx.x * 8];
            while (*f != gen) { __nanosleep(16); }
        }
        __threadfence();
    }
    __syncthreads();
}

extern __shared__ float smem[];

__device__ __forceinline__ uint32_t swz(uint32_t L) {
    return L ^ ((L >> 3) & 0x70u);
}

__global__ __launch_bounds__(NT, 1) void tts_kernel(
    const float* __restrict__ x_in,    // [B,T,D]
    const float* __restrict__ memv,    // [B,S,D]
    const int*   __restrict__ lens,    // [B]
    const float* __restrict__ W_ih,    // [4096,2048]
    const float* __restrict__ W_hh,    // [4096,1024]
    const float* __restrict__ b_ih,    // [4096]
    const float* __restrict__ b_hh,    // [4096]
    const float* __restrict__ Wg_w,    // [48,1024]
    const float* __restrict__ Wg_b,    // [48]
    float* __restrict__ out)
{
    const int bid = blockIdx.x;
    const int tid = threadIdx.x;
    char* smb = reinterpret_cast<char*>(smem);

    // scratch placed after the 4*CBB staging area (phase-disjoint with it)
    float* sh_phi   = smem + 6176;   // 48
    float* sh_ksi   = smem + 6224;   // 16
    float* sh_binv  = smem + 6240;   // 16
    float* sh_alpha = smem + 6256;   // 16

    float* out_ctx   = out;
    float* out_align = out + BB * DD;
    float* out_term  = out + BB * DD + (size_t)BB * TT * SS;

    int bgen = 0;

    for (int i = bid * NT + tid; i < BB * DD; i += NB * NT) {
        g_h[i] = 0.0f; g_c[i] = 0.0f; g_ctx[i] = 0.0f;
    }
    grid_barrier(++bgen);

    // mapping: 16 j-tiles (256 j each) x 8 k-splits (384 k each)
    const int jt = bid >> 3;            // 0..15
    const int kb = bid & 7;             // 0..7
    const int kbase = kb * KBL;

    const int jg    = tid >> 4;         // 0..31 -> 8 rows each
    const int lane4 = tid & 15;
    const int bg    = lane4 & 1;
    const int ksl   = lane4 >> 1;
    const int j0    = jt * 256 + jg * 8;

    const float* wih = W_ih + (size_t)j0 * 2048;
    const float* whh = W_hh + (size_t)j0 * 1024;

    // phase timers (cycles, accumulated over all steps)
    unsigned long long aS = 0, aG = 0, aB1 = 0, aP2 = 0, aB2 = 0, aP3 = 0, aB3 = 0;

    for (int t = 0; t < TT; ++t) {
        unsigned long long c0 = clock64();

        // ========== stage x slice [16 b x 384 k] (swizzled, float4 LDG) ====
        #pragma unroll
        for (int r = 0; r < 3; ++r) {
            const int qi = r * NT + tid;         // < 1536
            const int b  = qi / 96;
            const int kq = qi - b * 96;
            const int k  = kbase + kq * 4;
            float4 v;
            if (k < DD)
                v = *reinterpret_cast<const float4*>(&x_in[((size_t)b * TT + t) * DD + k]);
            else if (k < 2 * DD)
                v = *reinterpret_cast<const float4*>(&g_ctx[b * DD + (k - DD)]);
            else
                v = *reinterpret_cast<const float4*>(&g_h[b * DD + (k - 2 * DD)]);
            const int cb = b >> 2, bl = b & 3;
            char* base = smb + cb * CBB;
            const int kl = kq * 4;
            *reinterpret_cast<float*>(base + swz((uint32_t)((kl + 0) * 16 + bl * 4))) = v.x;
            *reinterpret_cast<float*>(base + swz((uint32_t)((kl + 1) * 16 + bl * 4))) = v.y;
            *reinterpret_cast<float*>(base + swz((uint32_t)((kl + 2) * 16 + bl * 4))) = v.z;
            *reinterpret_cast<float*>(base + swz((uint32_t)((kl + 3) * 16 + bl * 4))) = v.w;
        }
        __syncthreads();
        unsigned long long c1 = clock64();

        // ====== gates GEMM: 8 rows/thread, float2 weight double-buffer =====
        {
            unsigned long long acc[8][4];
            #pragma unroll
            for (int a = 0; a < 8; ++a)
                #pragma unroll
                for (int p = 0; p < 4; ++p) acc[a][p] = 0ull;

            float2 wA[8], wB[8];

            auto ldw = [&](float2* dst, int i) {
                const int k = kbase + (i * 8 + ksl) * 2;
                if (k < 2048) {
                    const float* p = wih + k;
                    #pragma unroll
                    for (int a = 0; a < 8; ++a)
                        dst[a] = *reinterpret_cast<const float2*>(p + (size_t)a * 2048);
                } else {
                    const float* p = whh + (k - 2048);
                    #pragma unroll
                    for (int a = 0; a < 8; ++a)
                        dst[a] = *reinterpret_cast<const float2*>(p + (size_t)a * 1024);
                }
            };

            const char* xb0 = smb + (bg * 2) * CBB;

            auto compute = [&](const float2* w, int i) {
                const int kp = i * 8 + ksl;
                #pragma unroll
                for (int q = 0; q < 2; ++q) {
                    const int kl = kp * 2 + q;
                    const uint32_t L = swz((uint32_t)(kl * 16));
                    const double2 d0 = *reinterpret_cast<const double2*>(xb0 + L);
                    const double2 d1 = *reinterpret_cast<const double2*>(xb0 + CBB + L);
                    const unsigned long long xv0 = __double_as_longlong(d0.x);
                    const unsigned long long xv1 = __double_as_longlong(d0.y);
                    const unsigned long long xv2 = __double_as_longlong(d1.x);
                    const unsigned long long xv3 = __double_as_longlong(d1.y);
                    #pragma unroll
                    for (int a = 0; a < 8; ++a) {
                        const float wv = q ? w[a].y : w[a].x;
                        unsigned long long w2;
                        asm("mov.b64 %0, {%1, %1};" : "=l"(w2) : "r"(__float_as_uint(wv)));
                        asm("fma.rn.f32x2 %0, %1, %2, %0;" : "+l"(acc[a][0]) : "l"(w2), "l"(xv0));
                        asm("fma.rn.f32x2 %0, %1, %2, %0;" : "+l"(acc[a][1]) : "l"(w2), "l"(xv1));
                        asm("fma.rn.f32x2 %0, %1, %2, %0;" : "+l"(acc[a][2]) : "l"(w2), "l"(xv2));
                        asm("fma.rn.f32x2 %0, %1, %2, %0;" : "+l"(acc[a][3]) : "l"(w2), "l"(xv3));
                    }
                }
            };

            ldw(wA, 0);
            #pragma unroll 1
            for (int ii = 0; ii < 12; ++ii) {
                ldw(wB, 2 * ii + 1);
                compute(wA, 2 * ii);
                if (ii < 11) ldw(wA, 2 * ii + 2);
                compute(wB, 2 * ii + 1);
            }

            #pragma unroll
            for (int off = 2; off <= 8; off <<= 1) {
                #pragma unroll
                for (int a = 0; a < 8; ++a)
                    #pragma unroll
                    for (int p = 0; p < 4; ++p) {
                        unsigned lo = (unsigned)acc[a][p];
                        unsigned hi = (unsigned)(acc[a][p] >> 32);
                        lo = __shfl_xor_sync(0xFFFFFFFFu, lo, off);
                        hi = __shfl_xor_sync(0xFFFFFFFFu, hi, off);
                        unsigned long long o = ((unsigned long long)hi << 32) | lo;
                        asm("add.rn.f32x2 %0, %0, %1;" : "+l"(acc[a][p]) : "l"(o));
                    }
            }

            #pragma unroll
            for (int a = 0; a < 8; ++a) {
                if (a == ksl) {
                    const int j = j0 + a;
                    #pragma unroll
                    for (int p = 0; p < 4; ++p) {
                        const int b0 = bg * 8 + 2 * p;
                        const unsigned long long v = acc[a][p];
                        g_gpart[kb][b0][j]     = __uint_as_float((unsigned)v);
                        g_gpart[kb][b0 + 1][j] = __uint_as_float((unsigned)(v >> 32));
                    }
                }
            }
        }
        unsigned long long c2 = clock64();
        grid_barrier(++bgen);  // B1: gates done
        unsigned long long c3 = clock64();

        // ============ LSTM + phi + GMM attention (blocks 0..15) ============
        if (bid < BB) {
            const int b = bid;
            {
                const int e = tid;          // element-pair index, 0..511
                const float2* bi = reinterpret_cast<const float2*>(b_ih);
                const float2* bh = reinterpret_cast<const float2*>(b_hh);
                float2 gi = bi[e],        gf = bi[512 + e];
                float2 gg = bi[1024 + e], go = bi[1536 + e];
                float2 v;
                v = bh[e];        gi.x += v.x; gi.y += v.y;
                v = bh[512 + e];  gf.x += v.x; gf.y += v.y;
                v = bh[1024 + e]; gg.x += v.x; gg.y += v.y;
                v = bh[1536 + e]; go.x += v.x; go.y += v.y;
                #pragma unroll
                for (int q = 0; q < KSPLIT; ++q) {
                    const float2* gp = reinterpret_cast<const float2*>(g_gpart[q][b]);
                    v = gp[e];        gi.x += v.x; gi.y += v.y;
                    v = gp[512 + e];  gf.x += v.x; gf.y += v.y;
                    v = gp[1024 + e]; gg.x += v.x; gg.y += v.y;
                    v = gp[1536 + e]; go.x += v.x; go.y += v.y;
                }
                float2* cp = reinterpret_cast<float2*>(g_c + b * DD);
                float2* hp = reinterpret_cast<float2*>(g_h + b * DD);
                const float2 cold = cp[e];
                float2 cn, hn;
                cn.x = sigf(gf.x) * cold.x + sigf(gi.x) * tanhfast(gg.x);
                cn.y = sigf(gf.y) * cold.y + sigf(gi.y) * tanhfast(gg.y);
                hn.x = sigf(go.x) * tanhfast(cn.x);
                hn.y = sigf(go.y) * tanhfast(cn.y);
                cp[e] = cn;
                hp[e] = hn;
            }
            __syncthreads();

            // phi = h @ Wg_w^T + Wg_b
            {
                const int w = tid >> 5, lane = tid & 31;
                float hreg[32];
                #pragma unroll
                for (int i = 0; i < 32; ++i) hreg[i] = g_h[b * DD + i * 32 + lane];
                #pragma unroll
                for (int mi = 0; mi < 3; ++mi) {
                    const int mm = w * 3 + mi;
                    const float* wr = Wg_w + (size_t)mm * DD;
                    float acc = 0.0f;
                    #pragma unroll
                    for (int i = 0; i < 32; ++i) acc += wr[i * 32 + lane] * hreg[i];
                    #pragma unroll
                    for (int off = 16; off; off >>= 1)
                        acc += __shfl_xor_sync(0xFFFFFFFFu, acc, off);
                    if (lane == 0) sh_phi[mm] = acc + Wg_b[mm];
                }
            }
            __syncthreads();

            if (tid < 32) {
                const int m = tid & 15;
                const float pk = sh_phi[m];
                const float pb = sh_phi[MM + m];
                const float pa = sh_phi[2 * MM + m];
                float mx = pa;
                #pragma unroll
                for (int off = 1; off < 16; off <<= 1)
                    mx = fmaxf(mx, __shfl_xor_sync(0xFFFFFFFFu, mx, off, 16));
                const float e = __expf(pa - mx);
                float sum = e;
                #pragma unroll
                for (int off = 1; off < 16; off <<= 1)
                    sum += __shfl_xor_sync(0xFFFFFFFFu, sum, off, 16);
                if (tid < 16) {
                    sh_alpha[m] = e / sum;
                    sh_ksi[m]   = __expf(pk);
                    sh_binv[m]  = __expf(-pb);
                }
            }
            __syncthreads();

            {
                const int s = tid & (SS - 1);
                const int lb = lens[b];
                const float fs = (float)s;
                float aw = 0.0f, ar = 0.0f;
                #pragma unroll
                for (int m = 0; m < MM; ++m) {
                    const float binv = sh_binv[m];
                    const float z  = (fs - sh_ksi[m]) * binv;
                    const float hb = 0.5f * binv;
                    const float fr = sigf(z + hb);
                    const float fl = sigf(z - hb);
                    const float al = sh_alpha[m];
                    aw += al * (fr - fl);
                    ar += al * fr;
                }
                g_watt[b][s] = aw;
                out_align[((size_t)b * TT + t) * SS + s] = aw;
                if (t == TT - 1 && s == lb - 1) out_term[b] = 1.0f - ar;
            }
        }
        unsigned long long c4 = clock64();
        grid_barrier(++bgen);  // B2: h, w ready
        unsigned long long c5 = clock64();

        // ===================== ctx = w @ memory ============================
        {
            const int b  = bid >> 3;
            const int d0 = (bid & 7) * 128;
            const int w  = tid >> 5, lane = tid & 31;
            const float* mb = memv + (size_t)b * SS * DD + d0 + lane * 4;
            float4 acc = make_float4(0.f, 0.f, 0.f, 0.f);
            const int sbase = w * 32;
            #pragma unroll 4
            for (int si = 0; si < 32; ++si) {
                const int s = sbase + si;
                const float wv = g_watt[b][s];
                const float4 mv = *reinterpret_cast<const float4*>(mb + (size_t)s * DD);
                acc.x += wv * mv.x; acc.y += wv * mv.y;
                acc.z += wv * mv.z; acc.w += wv * mv.w;
            }
            float4* red = reinterpret_cast<float4*>(smem);
            red[w * 32 + lane] = acc;
            __syncthreads();
            if (tid < 32) {
                float4 r = red[tid];
                #pragma unroll
                for (int q = 1; q < 16; ++q) {
                    const float4 v = red[q * 32 + tid];
                    r.x += v.x; r.y += v.y; r.z += v.z; r.w += v.w;
                }
                const int di = d0 + tid * 4;
                *reinterpret_cast<float4*>(&g_ctx[b * DD + di]) = r;
                if (t == TT - 1)
                    *reinterpret_cast<float4*>(&out_ctx[b * DD + di]) = r;
            }
        }
        unsigned long long c6 = clock64();
        grid_barrier(++bgen);  // B3: ctx ready
        unsigned long long c7 = clock64();

        aS  += c1 - c0;
        aG  += c2 - c1;
        aB1 += c3 - c2;
        aP2 += c4 - c3;
        aB2 += c5 - c4;
        aP3 += c6 - c5;
        aB3 += c7 - c6;

        if (t == TT - 1 && tid == 0 && (bid == 0 || bid == 100)) {
            printf("PHASE bid=%d stage=%llu gemm=%llu B1=%llu P2=%llu B2=%llu "
                   "P3=%llu B3=%llu (cyc total over %d steps)\n",
                   bid, aS, aG, aB1, aP2, aB2, aP3, aB3, TT);
        }
    }
}

extern "C" void kernel_launch(void* const* d_in, const int* in_sizes, int n_in,
                              void* d_out, int out_size) {
    (void)in_sizes; (void)n_in; (void)out_size;
    const float* x_in  = (const float*)d_in[0];
    const float* memv  = (const float*)d_in[1];
    const int*   lens  = (const int*)  d_in[2];
    const float* W_ih  = (const float*)d_in[3];
    const float* W_hh  = (const float*)d_in[4];
    const float* b_ih  = (const float*)d_in[5];
    const float* b_hh  = (const float*)d_in[6];
    const float* Wg_w  = (const float*)d_in[7];
    const float* Wg_b  = (const float*)d_in[8];
    tts_kernel<<<NB, NT, 28672>>>(x_in, memv, lens, W_ih, W_hh,
                                  b_ih, b_hh, Wg_w, Wg_b, (float*)d_out);
}

// round 11
// speedup vs baseline: 1.2134x; 1.1609x over previous
#include <cuda_runtime.h>
#include <cstdint>

#define NB 128
#define NT 512
#define BB 16
#define TT 1024
#define DD 1024
#define SS 512
#define MM 16
#define KSPLIT 8
#define KBL 384                    // k per block
#define CBB 6176                   // bytes per cb staging region (6144 + pad)

// ---------------- persistent state (device globals; no allocation) ----------
__device__ float g_h[BB * DD];
__device__ float g_cbuf[2][BB * DD];            // parity double buffer for c
__device__ float g_ctx[BB * DD];
__device__ float g_gpart[KSPLIT][BB][4 * DD];   // 2 MB
__device__ unsigned g_count;
__device__ int g_flags[NB * 8];

__device__ __forceinline__ float sigf(float x) {
    return __fdividef(1.0f, 1.0f + __expf(-x));
}
__device__ __forceinline__ float tanhfast(float x) {
    const float xc = fminf(fmaxf(x, -15.0f), 15.0f);
    const float e  = __expf(2.0f * xc);
    return __fdividef(e - 1.0f, e + 1.0f);
}

// Grid barrier with distributed release. 128 blocks, single wave.
__device__ __forceinline__ void grid_barrier(int gen) {
    __syncthreads();
    if (threadIdx.x == 0) {
        __threadfence();
        const unsigned arrived = atomicAdd(&g_count, 1u);
        if (arrived == NB - 1) {
            g_count = 0u;
            __threadfence();
            #pragma unroll 8
            for (int i = 0; i < NB; ++i) g_flags[i * 8] = gen;
        } else {
            volatile int* f = &g_flags[blockIdx.x * 8];
            while (*f != gen) { __nanosleep(16); }
        }
        __threadfence();
    }
    __syncthreads();
}

extern __shared__ float smem[];

__device__ __forceinline__ uint32_t swz(uint32_t L) {
    return L ^ ((L >> 3) & 0x70u);
}

__global__ __launch_bounds__(NT, 1) void tts_kernel(
    const float* __restrict__ x_in,    // [B,T,D]
    const float* __restrict__ memv,    // [B,S,D]
    const int*   __restrict__ lens,    // [B]
    const float* __restrict__ W_ih,    // [4096,2048]
    const float* __restrict__ W_hh,    // [4096,1024]
    const float* __restrict__ b_ih,    // [4096]
    const float* __restrict__ b_hh,    // [4096]
    const float* __restrict__ Wg_w,    // [48,1024]
    const float* __restrict__ Wg_b,    // [48]
    float* __restrict__ out)
{
    const int bid = blockIdx.x;
    const int tid = threadIdx.x;
    char* smb = reinterpret_cast<char*>(smem);

    // scratch after the 4*CBB staging area (24704 B -> float index 6176)
    float* sh_phi   = smem + 6176;   // 48
    float* sh_ksi   = smem + 6224;   // 16
    float* sh_binv  = smem + 6240;   // 16
    float* sh_alpha = smem + 6256;   // 16
    float* sh_h     = smem + 6272;   // 1024
    float* sh_watt  = smem + 7296;   // 512

    float* out_ctx   = out;
    float* out_align = out + BB * DD;
    float* out_term  = out + BB * DD + (size_t)BB * TT * SS;

    int bgen = 0;

    for (int i = bid * NT + tid; i < BB * DD; i += NB * NT) {
        g_h[i] = 0.0f; g_cbuf[0][i] = 0.0f; g_cbuf[1][i] = 0.0f; g_ctx[i] = 0.0f;
    }
    grid_barrier(++bgen);

    // GEMM mapping: 16 j-tiles (256 j each) x 8 k-splits (384 k each)
    const int jt = bid >> 3;            // 0..15
    const int kb = bid & 7;             // 0..7
    const int kbase = kb * KBL;

    const int jg    = tid >> 4;         // 0..31 -> 8 rows each
    const int lane4 = tid & 15;
    const int bg    = lane4 & 1;
    const int ksl   = lane4 >> 1;
    const int j0    = jt * 256 + jg * 8;

    const float* wih = W_ih + (size_t)j0 * 2048;
    const float* whh = W_hh + (size_t)j0 * 1024;

    // phase-2 mapping: every block owns (b2, d0); one writer block per b2
    const int  b2     = bid >> 3;
    const int  d0     = (bid & 7) * 128;
    const bool writer = (bid & 7) == 0;

    for (int t = 0; t < TT; ++t) {
        // ========== stage x slice [16 b x 384 k] (swizzled, float4 LDG) ====
        #pragma unroll
        for (int r = 0; r < 3; ++r) {
            const int qi = r * NT + tid;         // < 1536
            const int b  = qi / 96;
            const int kq = qi - b * 96;
            const int k  = kbase + kq * 4;
            float4 v;
            if (k < DD)
                v = *reinterpret_cast<const float4*>(&x_in[((size_t)b * TT + t) * DD + k]);
            else if (k < 2 * DD)
                v = *reinterpret_cast<const float4*>(&g_ctx[b * DD + (k - DD)]);
            else
                v = *reinterpret_cast<const float4*>(&g_h[b * DD + (k - 2 * DD)]);
            const int cb = b >> 2, bl = b & 3;
            char* base = smb + cb * CBB;
            const int kl = kq * 4;
            *reinterpret_cast<float*>(base + swz((uint32_t)((kl + 0) * 16 + bl * 4))) = v.x;
            *reinterpret_cast<float*>(base + swz((uint32_t)((kl + 1) * 16 + bl * 4))) = v.y;
            *reinterpret_cast<float*>(base + swz((uint32_t)((kl + 2) * 16 + bl * 4))) = v.z;
            *reinterpret_cast<float*>(base + swz((uint32_t)((kl + 3) * 16 + bl * 4))) = v.w;
        }
        __syncthreads();

        // ====== gates GEMM: 8 rows/thread, float2 weight double-buffer =====
        {
            unsigned long long acc[8][4];
            #pragma unroll
            for (int a = 0; a < 8; ++a)
                #pragma unroll
                for (int p = 0; p < 4; ++p) acc[a][p] = 0ull;

            float2 wA[8], wB[8];

            auto ldw = [&](float2* dst, int i) {
                const int k = kbase + (i * 8 + ksl) * 2;
                if (k < 2048) {
                    const float* p = wih + k;
                    #pragma unroll
                    for (int a = 0; a < 8; ++a)
                        dst[a] = *reinterpret_cast<const float2*>(p + (size_t)a * 2048);
                } else {
                    const float* p = whh + (k - 2048);
                    #pragma unroll
                    for (int a = 0; a < 8; ++a)
                        dst[a] = *reinterpret_cast<const float2*>(p + (size_t)a * 1024);
                }
            };

            const char* xb0 = smb + (bg * 2) * CBB;

            auto compute = [&](const float2* w, int i) {
                const int kp = i * 8 + ksl;
                #pragma unroll
                for (int q = 0; q < 2; ++q) {
                    const int kl = kp * 2 + q;
                    const uint32_t L = swz((uint32_t)(kl * 16));
                    const double2 d0v = *reinterpret_cast<const double2*>(xb0 + L);
                    const double2 d1v = *reinterpret_cast<const double2*>(xb0 + CBB + L);
                    const unsigned long long xv0 = __double_as_longlong(d0v.x);
                    const unsigned long long xv1 = __double_as_longlong(d0v.y);
                    const unsigned long long xv2 = __double_as_longlong(d1v.x);
                    const unsigned long long xv3 = __double_as_longlong(d1v.y);
                    #pragma unroll
                    for (int a = 0; a < 8; ++a) {
                        const float wv = q ? w[a].y : w[a].x;
                        unsigned long long w2;
                        asm("mov.b64 %0, {%1, %1};" : "=l"(w2) : "r"(__float_as_uint(wv)));
                        asm("fma.rn.f32x2 %0, %1, %2, %0;" : "+l"(acc[a][0]) : "l"(w2), "l"(xv0));
                        asm("fma.rn.f32x2 %0, %1, %2, %0;" : "+l"(acc[a][1]) : "l"(w2), "l"(xv1));
                        asm("fma.rn.f32x2 %0, %1, %2, %0;" : "+l"(acc[a][2]) : "l"(w2), "l"(xv2));
                        asm("fma.rn.f32x2 %0, %1, %2, %0;" : "+l"(acc[a][3]) : "l"(w2), "l"(xv3));
                    }
                }
            };

            ldw(wA, 0);
            #pragma unroll 1
            for (int ii = 0; ii < 12; ++ii) {
                ldw(wB, 2 * ii + 1);
                compute(wA, 2 * ii);
                if (ii < 11) ldw(wA, 2 * ii + 2);
                compute(wB, 2 * ii + 1);
            }

            #pragma unroll
            for (int off = 2; off <= 8; off <<= 1) {
                #pragma unroll
                for (int a = 0; a < 8; ++a)
                    #pragma unroll
                    for (int p = 0; p < 4; ++p) {
                        unsigned lo = (unsigned)acc[a][p];
                        unsigned hi = (unsigned)(acc[a][p] >> 32);
                        lo = __shfl_xor_sync(0xFFFFFFFFu, lo, off);
                        hi = __shfl_xor_sync(0xFFFFFFFFu, hi, off);
                        unsigned long long o = ((unsigned long long)hi << 32) | lo;
                        asm("add.rn.f32x2 %0, %0, %1;" : "+l"(acc[a][p]) : "l"(o));
                    }
            }

            #pragma unroll
            for (int a = 0; a < 8; ++a) {
                if (a == ksl) {
                    const int j = j0 + a;
                    #pragma unroll
                    for (int p = 0; p < 4; ++p) {
                        const int b0 = bg * 8 + 2 * p;
                        const unsigned long long v = acc[a][p];
                        g_gpart[kb][b0][j]     = __uint_as_float((unsigned)v);
                        g_gpart[kb][b0 + 1][j] = __uint_as_float((unsigned)(v >> 32));
                    }
                }
            }
        }
        grid_barrier(++bgen);  // B1: gates(t) complete

        // ===== fused phase: LSTM+phi+attn (redundant per b) + ctx GEMV =====
        {
            const float* cin  = g_cbuf[t & 1]       + b2 * DD;
            float*       cout = g_cbuf[(t & 1) ^ 1] + b2 * DD;

            #pragma unroll
            for (int r = 0; r < 2; ++r) {
                const int dd = r * NT + tid;
                float gi = b_ih[dd]          + b_hh[dd];
                float gf = b_ih[DD + dd]     + b_hh[DD + dd];
                float gg = b_ih[2 * DD + dd] + b_hh[2 * DD + dd];
                float go = b_ih[3 * DD + dd] + b_hh[3 * DD + dd];
                #pragma unroll
                for (int q = 0; q < KSPLIT; ++q) {
                    gi += g_gpart[q][b2][dd];
                    gf += g_gpart[q][b2][DD + dd];
                    gg += g_gpart[q][b2][2 * DD + dd];
                    go += g_gpart[q][b2][3 * DD + dd];
                }
                const float c = sigf(gf) * cin[dd] + sigf(gi) * tanhfast(gg);
                const float h = sigf(go) * tanhfast(c);
                sh_h[dd] = h;
                if (writer) { cout[dd] = c; g_h[b2 * DD + dd] = h; }
            }
            __syncthreads();

            // phi = h @ Wg_w^T + Wg_b  (16 warps x 3 rows)
            {
                const int w = tid >> 5, lane = tid & 31;
                float hreg[32];
                #pragma unroll
                for (int i = 0; i < 32; ++i) hreg[i] = sh_h[i * 32 + lane];
                #pragma unroll
                for (int mi = 0; mi < 3; ++mi) {
                    const int mm = w * 3 + mi;
                    const float* wr = Wg_w + (size_t)mm * DD;
                    float acc = 0.0f;
                    #pragma unroll
                    for (int i = 0; i < 32; ++i) acc += wr[i * 32 + lane] * hreg[i];
                    #pragma unroll
                    for (int off = 16; off; off >>= 1)
                        acc += __shfl_xor_sync(0xFFFFFFFFu, acc, off);
                    if (lane == 0) sh_phi[mm] = acc + Wg_b[mm];
                }
            }
            __syncthreads();

            if (tid < 32) {
                const int m = tid & 15;
                const float pk = sh_phi[m];
                const float pb = sh_phi[MM + m];
                const float pa = sh_phi[2 * MM + m];
                float mx = pa;
                #pragma unroll
                for (int off = 1; off < 16; off <<= 1)
                    mx = fmaxf(mx, __shfl_xor_sync(0xFFFFFFFFu, mx, off, 16));
                const float e = __expf(pa - mx);
                float sum = e;
                #pragma unroll
                for (int off = 1; off < 16; off <<= 1)
                    sum += __shfl_xor_sync(0xFFFFFFFFu, sum, off, 16);
                if (tid < 16) {
                    sh_alpha[m] = e / sum;
                    sh_ksi[m]   = __expf(pk);
                    sh_binv[m]  = __expf(-pb);
                }
            }
            __syncthreads();

            // attention weights (one s per thread, into smem)
            {
                const int s = tid;            // NT == SS
                const float fs = (float)s;
                float aw = 0.0f, ar = 0.0f;
                #pragma unroll
                for (int m = 0; m < MM; ++m) {
                    const float binv = sh_binv[m];
                    const float z  = (fs - sh_ksi[m]) * binv;
                    const float hb = 0.5f * binv;
                    const float fr = sigf(z + hb);
                    const float fl = sigf(z - hb);
                    const float al = sh_alpha[m];
                    aw += al * (fr - fl);
                    ar += al * fr;
                }
                sh_watt[s] = aw;
                if (writer) {
                    out_align[((size_t)b2 * TT + t) * SS + s] = aw;
                    if (t == TT - 1 && s == lens[b2] - 1) out_term[b2] = 1.0f - ar;
                }
            }
            __syncthreads();

            // ctx GEMV: this block's (b2, d0) slice, watt from smem
            {
                const int w = tid >> 5, lane = tid & 31;
                const float* mb = memv + (size_t)b2 * SS * DD + d0 + lane * 4;
                float4 acc = make_float4(0.f, 0.f, 0.f, 0.f);
                const int sbase = w * 32;
                #pragma unroll 4
                for (int si = 0; si < 32; ++si) {
                    const int s = sbase + si;
                    const float wv = sh_watt[s];
                    const float4 mv = *reinterpret_cast<const float4*>(mb + (size_t)s * DD);
                    acc.x += wv * mv.x; acc.y += wv * mv.y;
                    acc.z += wv * mv.z; acc.w += wv * mv.w;
                }
                float4* red = reinterpret_cast<float4*>(smem);  // staging area is dead here
                red[w * 32 + lane] = acc;
                __syncthreads();
                if (tid < 32) {
                    float4 r = red[tid];
                    #pragma unroll
                    for (int q = 1; q < 16; ++q) {
                        const float4 v = red[q * 32 + tid];
                        r.x += v.x; r.y += v.y; r.z += v.z; r.w += v.w;
                    }
                    const int di = d0 + tid * 4;
                    *reinterpret_cast<float4*>(&g_ctx[b2 * DD + di]) = r;
                    if (t == TT - 1)
                        *reinterpret_cast<float4*>(&out_ctx[b2 * DD + di]) = r;
                }
            }
        }
        grid_barrier(++bgen);  // B3: h, c, ctx ready for next step
    }
}

extern "C" void kernel_launch(void* const* d_in, const int* in_sizes, int n_in,
                              void* d_out, int out_size) {
    (void)in_sizes; (void)n_in; (void)out_size;
    const float* x_in  = (const float*)d_in[0];
    const float* memv  = (const float*)d_in[1];
    const int*   lens  = (const int*)  d_in[2];
    const float* W_ih  = (const float*)d_in[3];
    const float* W_hh  = (const float*)d_in[4];
    const float* b_ih  = (const float*)d_in[5];
    const float* b_hh  = (const float*)d_in[6];
    const float* Wg_w  = (const float*)d_in[7];
    const float* Wg_b  = (const float*)d_in[8];
    tts_kernel<<<NB, NT, 32768>>>(x_in, memv, lens, W_ih, W_hh,
                                  b_ih, b_hh, Wg_w, Wg_b, (float*)d_out);
}

// round 12
// speedup vs baseline: 1.2773x; 1.0526x over previous
#include <cuda_runtime.h>
#include <cstdint>

#define NB 128
#define NT 512
#define BB 16
#define TT 1024
#define DD 1024
#define SS 512
#define MM 16
#define KSPLIT 8
#define KBL 384                    // k per block
#define CBB 6176                   // bytes per cb staging region (6144 + pad)

// ---------------- persistent state (device globals; no allocation) ----------
__device__ float g_h[BB * DD];
__device__ float g_cbuf[2][BB * DD];            // parity double buffer for c
__device__ float g_ctx[BB * DD];
__device__ float g_bias[4 * DD];
__device__ float g_gpart[KSPLIT][BB][4 * DD];   // 2 MB
__device__ unsigned g_cnt_grp[8 * 32];          // group counters, 128B apart
__device__ unsigned g_cnt_root;
__device__ int g_flags[NB * 8];

__device__ __forceinline__ float sigf(float x) {
    return __fdividef(1.0f, 1.0f + __expf(-x));
}
__device__ __forceinline__ float tanhfast(float x) {
    const float xc = fminf(fmaxf(x, -15.0f), 15.0f);
    const float e  = __expf(2.0f * xc);
    return __fdividef(e - 1.0f, e + 1.0f);
}

// Grid barrier: tree arrival (8 groups of 16 -> root), distributed release.
// 128 blocks <= 148 SMs => single wave, all co-resident.
__device__ __forceinline__ void grid_barrier(int gen) {
    __syncthreads();
    if (threadIdx.x == 0) {
        __threadfence();
        const int g = blockIdx.x >> 4;
        if (atomicAdd(&g_cnt_grp[g * 32], 1u) == 15u) {
            g_cnt_grp[g * 32] = 0u;
            if (atomicAdd(&g_cnt_root, 1u) == 7u) {
                g_cnt_root = 0u;
                __threadfence();
                #pragma unroll 8
                for (int i = 0; i < NB; ++i) g_flags[i * 8] = gen;
            }
        }
        volatile int* f = &g_flags[blockIdx.x * 8];
        while (*f != gen) { __nanosleep(16); }
        __threadfence();
    }
    __syncthreads();
}

extern __shared__ float smem[];

__device__ __forceinline__ uint32_t swz(uint32_t L) {
    return L ^ ((L >> 3) & 0x70u);
}

__global__ __launch_bounds__(NT, 1) void tts_kernel(
    const float* __restrict__ x_in,    // [B,T,D]
    const float* __restrict__ memv,    // [B,S,D]
    const int*   __restrict__ lens,    // [B]
    const float* __restrict__ W_ih,    // [4096,2048]
    const float* __restrict__ W_hh,    // [4096,1024]
    const float* __restrict__ b_ih,    // [4096]
    const float* __restrict__ b_hh,    // [4096]
    const float* __restrict__ Wg_w,    // [48,1024]
    const float* __restrict__ Wg_b,    // [48]
    float* __restrict__ out)
{
    const int bid = blockIdx.x;
    const int tid = threadIdx.x;
    char* smb = reinterpret_cast<char*>(smem);

    // scratch after the 4*CBB staging area (24704 B -> float index 6176)
    float* sh_phi   = smem + 6176;   // 48
    float* sh_ksi   = smem + 6224;   // 16
    float* sh_binv  = smem + 6240;   // 16
    float* sh_alpha = smem + 6256;   // 16
    float* sh_h     = smem + 6272;   // 1024
    float* sh_watt  = smem + 7296;   // 512
    int*   sh_skip  = reinterpret_cast<int*>(smem + 7808);  // 16

    float* out_ctx   = out;
    float* out_align = out + BB * DD;
    float* out_term  = out + BB * DD + (size_t)BB * TT * SS;

    int bgen = 0;

    for (int i = bid * NT + tid; i < BB * DD; i += NB * NT) {
        g_h[i] = 0.0f; g_cbuf[0][i] = 0.0f; g_cbuf[1][i] = 0.0f; g_ctx[i] = 0.0f;
    }
    for (int i = bid * NT + tid; i < 4 * DD; i += NB * NT)
        g_bias[i] = b_ih[i] + b_hh[i];
    grid_barrier(++bgen);

    // GEMM mapping: 16 j-tiles (256 j each) x 8 k-splits (384 k each)
    const int jt = bid >> 3;            // 0..15
    const int kb = bid & 7;             // 0..7
    const int kbase = kb * KBL;

    const int jg    = tid >> 4;         // 0..31 -> 8 rows each
    const int lane4 = tid & 15;
    const int bg    = lane4 & 1;
    const int ksl   = lane4 >> 1;
    const int j0    = jt * 256 + jg * 8;

    const float* wih = W_ih + (size_t)j0 * 2048;
    const float* whh = W_hh + (size_t)j0 * 1024;

    // phase-2 mapping: every block owns (b2, d0); one writer block per b2
    const int  b2     = bid >> 3;
    const int  d0     = (bid & 7) * 128;
    const bool writer = (bid & 7) == 0;

    for (int t = 0; t < TT; ++t) {
        // ========== stage x slice [16 b x 384 k] (swizzled, float4 LDG) ====
        #pragma unroll
        for (int r = 0; r < 3; ++r) {
            const int qi = r * NT + tid;         // < 1536
            const int b  = qi / 96;
            const int kq = qi - b * 96;
            const int k  = kbase + kq * 4;
            float4 v;
            if (k < DD)
                v = *reinterpret_cast<const float4*>(&x_in[((size_t)b * TT + t) * DD + k]);
            else if (k < 2 * DD)
                v = *reinterpret_cast<const float4*>(&g_ctx[b * DD + (k - DD)]);
            else
                v = *reinterpret_cast<const float4*>(&g_h[b * DD + (k - 2 * DD)]);
            const int cb = b >> 2, bl = b & 3;
            char* base = smb + cb * CBB;
            const int kl = kq * 4;
            *reinterpret_cast<float*>(base + swz((uint32_t)((kl + 0) * 16 + bl * 4))) = v.x;
            *reinterpret_cast<float*>(base + swz((uint32_t)((kl + 1) * 16 + bl * 4))) = v.y;
            *reinterpret_cast<float*>(base + swz((uint32_t)((kl + 2) * 16 + bl * 4))) = v.z;
            *reinterpret_cast<float*>(base + swz((uint32_t)((kl + 3) * 16 + bl * 4))) = v.w;
        }
        __syncthreads();

        // ====== gates GEMM: 8 rows/thread, float2 weight double-buffer =====
        {
            unsigned long long acc[8][4];
            #pragma unroll
            for (int a = 0; a < 8; ++a)
                #pragma unroll
                for (int p = 0; p < 4; ++p) acc[a][p] = 0ull;

            float2 wA[8], wB[8];

            auto ldw = [&](float2* dst, int i) {
                const int k = kbase + (i * 8 + ksl) * 2;
                if (k < 2048) {
                    const float* p = wih + k;
                    #pragma unroll
                    for (int a = 0; a < 8; ++a)
                        dst[a] = *reinterpret_cast<const float2*>(p + (size_t)a * 2048);
                } else {
                    const float* p = whh + (k - 2048);
                    #pragma unroll
                    for (int a = 0; a < 8; ++a)
                        dst[a] = *reinterpret_cast<const float2*>(p + (size_t)a * 1024);
                }
            };

            const char* xb0 = smb + (bg * 2) * CBB;

            auto compute = [&](const float2* w, int i) {
                const int kp = i * 8 + ksl;
                #pragma unroll
                for (int q = 0; q < 2; ++q) {
                    const int kl = kp * 2 + q;
                    const uint32_t L = swz((uint32_t)(kl * 16));
                    const double2 d0v = *reinterpret_cast<const double2*>(xb0 + L);
                    const double2 d1v = *reinterpret_cast<const double2*>(xb0 + CBB + L);
                    const unsigned long long xv0 = __double_as_longlong(d0v.x);
                    const unsigned long long xv1 = __double_as_longlong(d0v.y);
                    const unsigned long long xv2 = __double_as_longlong(d1v.x);
                    const unsigned long long xv3 = __double_as_longlong(d1v.y);
                    #pragma unroll
                    for (int a = 0; a < 8; ++a) {
                        const float wv = q ? w[a].y : w[a].x;
                        unsigned long long w2;
                        asm("mov.b64 %0, {%1, %1};" : "=l"(w2) : "r"(__float_as_uint(wv)));
                        asm("fma.rn.f32x2 %0, %1, %2, %0;" : "+l"(acc[a][0]) : "l"(w2), "l"(xv0));
                        asm("fma.rn.f32x2 %0, %1, %2, %0;" : "+l"(acc[a][1]) : "l"(w2), "l"(xv1));
                        asm("fma.rn.f32x2 %0, %1, %2, %0;" : "+l"(acc[a][2]) : "l"(w2), "l"(xv2));
                        asm("fma.rn.f32x2 %0, %1, %2, %0;" : "+l"(acc[a][3]) : "l"(w2), "l"(xv3));
                    }
                }
            };

            ldw(wA, 0);
            #pragma unroll 1
            for (int ii = 0; ii < 12; ++ii) {
                ldw(wB, 2 * ii + 1);
                compute(wA, 2 * ii);
                if (ii < 11) ldw(wA, 2 * ii + 2);
                compute(wB, 2 * ii + 1);
            }

            #pragma unroll
            for (int off = 2; off <= 8; off <<= 1) {
                #pragma unroll
                for (int a = 0; a < 8; ++a)
                    #pragma unroll
                    for (int p = 0; p < 4; ++p) {
                        unsigned lo = (unsigned)acc[a][p];
                        unsigned hi = (unsigned)(acc[a][p] >> 32);
                        lo = __shfl_xor_sync(0xFFFFFFFFu, lo, off);
                        hi = __shfl_xor_sync(0xFFFFFFFFu, hi, off);
                        unsigned long long o = ((unsigned long long)hi << 32) | lo;
                        asm("add.rn.f32x2 %0, %0, %1;" : "+l"(acc[a][p]) : "l"(o));
                    }
            }

            #pragma unroll
            for (int a = 0; a < 8; ++a) {
                if (a == ksl) {
                    const int j = j0 + a;
                    #pragma unroll
                    for (int p = 0; p < 4; ++p) {
                        const int b0 = bg * 8 + 2 * p;
                        const unsigned long long v = acc[a][p];
                        g_gpart[kb][b0][j]     = __uint_as_float((unsigned)v);
                        g_gpart[kb][b0 + 1][j] = __uint_as_float((unsigned)(v >> 32));
                    }
                }
            }
        }
        grid_barrier(++bgen);  // B1: gates(t) complete

        // ===== fused phase: LSTM+phi+attn (redundant per b) + ctx GEMV =====
        {
            const float* cin  = g_cbuf[t & 1]       + b2 * DD;
            float*       cout = g_cbuf[(t & 1) ^ 1] + b2 * DD;

            #pragma unroll
            for (int r = 0; r < 2; ++r) {
                const int dd = r * NT + tid;
                float gi = g_bias[dd];
                float gf = g_bias[DD + dd];
                float gg = g_bias[2 * DD + dd];
                float go = g_bias[3 * DD + dd];
                #pragma unroll
                for (int q = 0; q < KSPLIT; ++q) {
                    gi += g_gpart[q][b2][dd];
                    gf += g_gpart[q][b2][DD + dd];
                    gg += g_gpart[q][b2][2 * DD + dd];
                    go += g_gpart[q][b2][3 * DD + dd];
                }
                const float c = sigf(gf) * cin[dd] + sigf(gi) * tanhfast(gg);
                const float h = sigf(go) * tanhfast(c);
                sh_h[dd] = h;
                if (writer) { cout[dd] = c; g_h[b2 * DD + dd] = h; }
            }
            __syncthreads();

            // phi = h @ Wg_w^T + Wg_b  (16 warps x 3 rows)
            {
                const int w = tid >> 5, lane = tid & 31;
                float hreg[32];
                #pragma unroll
                for (int i = 0; i < 32; ++i) hreg[i] = sh_h[i * 32 + lane];
                #pragma unroll
                for (int mi = 0; mi < 3; ++mi) {
                    const int mm = w * 3 + mi;
                    const float* wr = Wg_w + (size_t)mm * DD;
                    float acc = 0.0f;
                    #pragma unroll
                    for (int i = 0; i < 32; ++i) acc += wr[i * 32 + lane] * hreg[i];
                    #pragma unroll
                    for (int off = 16; off; off >>= 1)
                        acc += __shfl_xor_sync(0xFFFFFFFFu, acc, off);
                    if (lane == 0) sh_phi[mm] = acc + Wg_b[mm];
                }
            }
            __syncthreads();

            if (tid < 32) {
                const int m = tid & 15;
                const float pk = sh_phi[m];
                const float pb = sh_phi[MM + m];
                const float pa = sh_phi[2 * MM + m];
                float mx = pa;
                #pragma unroll
                for (int off = 1; off < 16; off <<= 1)
                    mx = fmaxf(mx, __shfl_xor_sync(0xFFFFFFFFu, mx, off, 16));
                const float e = __expf(pa - mx);
                float sum = e;
                #pragma unroll
                for (int off = 1; off < 16; off <<= 1)
                    sum += __shfl_xor_sync(0xFFFFFFFFu, sum, off, 16);
                if (tid < 16) {
                    sh_alpha[m] = e / sum;
                    sh_ksi[m]   = __expf(pk);
                    sh_binv[m]  = __expf(-pb);
                }
            }
            __syncthreads();

            // attention weights (one s per thread) + warp-chunk skip flags
            {
                const int s = tid;            // NT == SS
                const int w = tid >> 5, lane = tid & 31;
                const float fs = (float)s;
                float aw = 0.0f, ar = 0.0f;
                #pragma unroll
                for (int m = 0; m < MM; ++m) {
                    const float binv = sh_binv[m];
                    const float z  = (fs - sh_ksi[m]) * binv;
                    const float hb = 0.5f * binv;
                    const float fr = sigf(z + hb);
                    const float fl = sigf(z - hb);
                    const float al = sh_alpha[m];
                    aw += al * (fr - fl);
                    ar += al * fr;
                }
                sh_watt[s] = aw;
                float mx = aw;
                #pragma unroll
                for (int off = 16; off; off >>= 1)
                    mx = fmaxf(mx, __shfl_xor_sync(0xFFFFFFFFu, mx, off));
                if (lane == 0) sh_skip[w] = (mx < 1e-8f);
                if (writer) {
                    out_align[((size_t)b2 * TT + t) * SS + s] = aw;
                    if (t == TT - 1 && s == lens[b2] - 1) out_term[b2] = 1.0f - ar;
                }
            }
            __syncthreads();

            // ctx GEMV: this block's (b2, d0) slice; skip near-zero s chunks
            {
                const int w = tid >> 5, lane = tid & 31;
                float4 acc = make_float4(0.f, 0.f, 0.f, 0.f);
                if (!sh_skip[w]) {
                    const float* mb = memv + (size_t)b2 * SS * DD + d0 + lane * 4;
                    const int sbase = w * 32;
                    #pragma unroll 4
                    for (int si = 0; si < 32; ++si) {
                        const int s = sbase + si;
                        const float wv = sh_watt[s];
                        const float4 mv = *reinterpret_cast<const float4*>(mb + (size_t)s * DD);
                        acc.x += wv * mv.x; acc.y += wv * mv.y;
                        acc.z += wv * mv.z; acc.w += wv * mv.w;
                    }
                }
                float4* red = reinterpret_cast<float4*>(smem);  // staging dead here
                red[w * 32 + lane] = acc;
                __syncthreads();
                if (tid < 32) {
                    float4 r = red[tid];
                    #pragma unroll
                    for (int q = 1; q < 16; ++q) {
                        const float4 v = red[q * 32 + tid];
                        r.x += v.x; r.y += v.y; r.z += v.z; r.w += v.w;
                    }
                    const int di = d0 + tid * 4;
                    *reinterpret_cast<float4*>(&g_ctx[b2 * DD + di]) = r;
                    if (t == TT - 1)
                        *reinterpret_cast<float4*>(&out_ctx[b2 * DD + di]) = r;
                }
            }
        }
        grid_barrier(++bgen);  // B3: h, c, ctx ready for next step
    }
}

extern "C" void kernel_launch(void* const* d_in, const int* in_sizes, int n_in,
                              void* d_out, int out_size) {
    (void)in_sizes; (void)n_in; (void)out_size;
    const float* x_in  = (const float*)d_in[0];
    const float* memv  = (const float*)d_in[1];
    const int*   lens  = (const int*)  d_in[2];
    const float* W_ih  = (const float*)d_in[3];
    const float* W_hh  = (const float*)d_in[4];
    const float* b_ih  = (const float*)d_in[5];
    const float* b_hh  = (const float*)d_in[6];
    const float* Wg_w  = (const float*)d_in[7];
    const float* Wg_b  = (const float*)d_in[8];
    tts_kernel<<<NB, NT, 32768>>>(x_in, memv, lens, W_ih, W_hh,
                                  b_ih, b_hh, Wg_w, Wg_b, (float*)d_out);
}